// round 2
// baseline (speedup 1.0000x reference)
#include <cuda_runtime.h>
#include <cstddef>

// ---------------------------------------------------------------------------
// Compile-time Gaussian weights (so ptxas emits FFMA-imm, rt=1)
// ---------------------------------------------------------------------------
constexpr double cexp_pos(double x) {
    // exp(x) for x >= 0 via all-positive Taylor series (x <= ~13 here).
    // Early break before term underflows (constexpr eval rejects FP underflow).
    double term = 1.0, sum = 1.0;
    for (int i = 1; i < 200; ++i) {
        term *= x / (double)i;
        if (term < 1e-250) break;
        sum += term;
    }
    return sum;
}

template <int KS>
struct Wt { float w[KS]; };

template <int KS>
constexpr Wt<KS> make_w(double sigma) {
    Wt<KS> W{};
    double wd[KS]{};
    double s = 0.0;
    for (int i = 0; i < KS; ++i) {
        double d = (double)(i - KS / 2);
        double e = 1.0 / cexp_pos(d * d / (2.0 * sigma * sigma));
        wd[i] = e;
        s += e;
    }
    for (int i = 0; i < KS; ++i) W.w[i] = (float)(wd[i] / s);
    return W;
}

// sigma scales 0.6 * 2^i ; ks = max(7, 2*ceil(3*sigma)+1)
__device__ constexpr Wt<7>   W0 = make_w<7>(0.6);
__device__ constexpr Wt<9>   W1 = make_w<9>(1.2);
__device__ constexpr Wt<17>  W2 = make_w<17>(2.4);
__device__ constexpr Wt<31>  W3 = make_w<31>(4.8);
__device__ constexpr Wt<59>  W4 = make_w<59>(9.6);
__device__ constexpr Wt<117> W5 = make_w<117>(19.2);

constexpr int H = 512, W = 512;
constexpr int HW = H * W;               // 262144
constexpr int NROWS = 8 * 3 * H;        // 12288 rows total
constexpr int NPIX = NROWS * W;         // 6291456
constexpr int PMAX = 58;                // max halo (ks=117)

// 6 horizontally-blurred planes
__device__ float g_scratch[6 * (size_t)NPIX];

// ---------------------------------------------------------------------------
// Kernel A: horizontal pass. CTA = 256 threads = 4 rows x 64 threads.
// Each thread computes 8 consecutive pixels for all 6 sigmas.
// smem row is padded (idx -> idx + idx/8) so stride-8 lane access is
// conflict-free (effective lane stride 9, coprime with 32 banks).
// ---------------------------------------------------------------------------
template <int KS>
__device__ __forceinline__ void hconv(const float (&Wc)[KS],
                                      const float* __restrict__ sr,
                                      int lane, float* __restrict__ dst) {
    constexpr int P  = KS / 2;
    constexpr int S0 = PMAX - P;          // buffer offset of output x=0 tap k=0
    constexpr int Q  = S0 >> 3;
    constexpr int R  = S0 & 7;
    const int base = 9 * (lane + Q);      // padded base; offsets below fold to imm

    float win[8], acc[8];
#pragma unroll
    for (int i = 0; i < 7; ++i)
        win[i] = sr[base + (R + i) + ((R + i) >> 3)];
#pragma unroll
    for (int t = 0; t < 8; ++t) acc[t] = 0.f;
#pragma unroll
    for (int k = 0; k < KS; ++k) {
        const int j = k + 7;
        win[j & 7] = sr[base + (R + j) + ((R + j) >> 3)];
#pragma unroll
        for (int t = 0; t < 8; ++t)
            acc[t] += Wc[k] * win[(k + t) & 7];
    }
    float4* d4 = reinterpret_cast<float4*>(dst + lane * 8);
    d4[0] = make_float4(acc[0], acc[1], acc[2], acc[3]);
    d4[1] = make_float4(acc[4], acc[5], acc[6], acc[7]);
}

__global__ __launch_bounds__(256) void hpass_kernel(const float* __restrict__ img) {
    __shared__ float sr[4][712];          // 628 valid + pad(78) = 706, round up
    const int grp = threadIdx.x >> 6;     // row within CTA
    const int lt  = threadIdx.x & 63;     // lane within row (64 threads/row)
    const int row = blockIdx.x * 4 + grp;

    const float* rp = img + (size_t)row * W;
    for (int x = lt; x < W + 2 * PMAX; x += 64) {
        int gx = x - PMAX;
        gx = gx < 0 ? -gx : (gx > H - 1 ? 2 * H - 2 - gx : gx);
        sr[grp][x + (x >> 3)] = rp[gx];
    }
    __syncthreads();

    const float* s = sr[grp];
    float* base = g_scratch + (size_t)row * W;
    hconv<7>(W0.w, s, lt, base + 0 * (size_t)NPIX);
    hconv<9>(W1.w, s, lt, base + 1 * (size_t)NPIX);
    hconv<17>(W2.w, s, lt, base + 2 * (size_t)NPIX);
    hconv<31>(W3.w, s, lt, base + 3 * (size_t)NPIX);
    hconv<59>(W4.w, s, lt, base + 4 * (size_t)NPIX);
    hconv<117>(W5.w, s, lt, base + 5 * (size_t)NPIX);
}

// ---------------------------------------------------------------------------
// Kernel B: vertical pass + DoG subbands.
// CTA = 256 threads: 8 warps, warp g handles output rows [g*8, g*8+8) of a
// 64-row x 32-col tile; lane = column. Per sigma: stage hb_s tile (+halo) in
// smem, vertical conv with rolling 8-reg window, emit subband = G_s - prev.
// ---------------------------------------------------------------------------
template <int KS>
__device__ __forceinline__ void load_tile(float* __restrict__ sm,
                                          const float* __restrict__ src,
                                          int R0, int tid) {
    constexpr int P = KS / 2;
    constexpr int NR = 64 + KS - 1;
    for (int idx = tid; idx < NR * 32; idx += 256) {
        const int m = idx >> 5, cc = idx & 31;
        int gr = R0 - P + m;
        gr = gr < 0 ? -gr : (gr > H - 1 ? 2 * H - 2 - gr : gr);
        sm[idx] = src[(size_t)gr * W + cc];
    }
}

template <int KS>
__device__ __forceinline__ void vconv(const float (&Wc)[KS],
                                      const float* __restrict__ sm,
                                      int g, int lane, float acc[8]) {
    const int base = g * 8 * 32 + lane;
    float win[8];
#pragma unroll
    for (int i = 0; i < 7; ++i) win[i] = sm[base + i * 32];
#pragma unroll
    for (int t = 0; t < 8; ++t) acc[t] = 0.f;
#pragma unroll
    for (int k = 0; k < KS; ++k) {
        win[(k + 7) & 7] = sm[base + (k + 7) * 32];
#pragma unroll
        for (int t = 0; t < 8; ++t)
            acc[t] += Wc[k] * win[(k + t) & 7];
    }
}

__device__ __forceinline__ void store_sub(float* __restrict__ p,
                                          const float acc[8], float prev[8]) {
#pragma unroll
    for (int t = 0; t < 8; ++t) {
        p[(size_t)t * W] = acc[t] - prev[t];
        prev[t] = acc[t];
    }
}

__global__ __launch_bounds__(256) void vpass_kernel(const float* __restrict__ img,
                                                    float* __restrict__ out) {
    __shared__ float sm[180 * 32];        // max tile: (64 + 116) rows x 32 cols

    const int lane = threadIdx.x & 31;
    const int g    = threadIdx.x >> 5;
    const int c0   = blockIdx.x * 32;
    const int R0   = blockIdx.y * 64;
    const int bc   = blockIdx.z;          // b*3 + ch
    const int b    = bc / 3;
    const int ch   = bc - b * 3;
    const int rbase = R0 + g * 8;

    // original image values (for subband 0 = G0 - img)
    const float* imgp = img + (size_t)bc * HW + c0 + lane;
    float prev[8], acc[8];
#pragma unroll
    for (int t = 0; t < 8; ++t) prev[t] = imgp[(size_t)(rbase + t) * W];

    // out[b][sb][ch][r][c] : sb stride = 3*HW
    float* outp = out + ((size_t)b * 21 + ch) * HW + (size_t)rbase * W + c0 + lane;
    const float* sbase = g_scratch + (size_t)bc * HW + c0;

    load_tile<7>(sm, sbase + 0 * (size_t)NPIX, R0, threadIdx.x);
    __syncthreads();
    vconv<7>(W0.w, sm, g, lane, acc);
    store_sub(outp + 0 * (size_t)(3 * HW), acc, prev);
    __syncthreads();

    load_tile<9>(sm, sbase + 1 * (size_t)NPIX, R0, threadIdx.x);
    __syncthreads();
    vconv<9>(W1.w, sm, g, lane, acc);
    store_sub(outp + 1 * (size_t)(3 * HW), acc, prev);
    __syncthreads();

    load_tile<17>(sm, sbase + 2 * (size_t)NPIX, R0, threadIdx.x);
    __syncthreads();
    vconv<17>(W2.w, sm, g, lane, acc);
    store_sub(outp + 2 * (size_t)(3 * HW), acc, prev);
    __syncthreads();

    load_tile<31>(sm, sbase + 3 * (size_t)NPIX, R0, threadIdx.x);
    __syncthreads();
    vconv<31>(W3.w, sm, g, lane, acc);
    store_sub(outp + 3 * (size_t)(3 * HW), acc, prev);
    __syncthreads();

    load_tile<59>(sm, sbase + 4 * (size_t)NPIX, R0, threadIdx.x);
    __syncthreads();
    vconv<59>(W4.w, sm, g, lane, acc);
    store_sub(outp + 4 * (size_t)(3 * HW), acc, prev);
    __syncthreads();

    load_tile<117>(sm, sbase + 5 * (size_t)NPIX, R0, threadIdx.x);
    __syncthreads();
    vconv<117>(W5.w, sm, g, lane, acc);
    store_sub(outp + 5 * (size_t)(3 * HW), acc, prev);

    // last subband = G5 itself (prev now holds G5)
#pragma unroll
    for (int t = 0; t < 8; ++t)
        outp[6 * (size_t)(3 * HW) + (size_t)t * W] = prev[t];
}

// ---------------------------------------------------------------------------
extern "C" void kernel_launch(void* const* d_in, const int* in_sizes, int n_in,
                              void* d_out, int out_size) {
    const float* img = (const float*)d_in[0];
    float* out = (float*)d_out;

    hpass_kernel<<<NROWS / 4, 256>>>(img);
    vpass_kernel<<<dim3(W / 32, H / 64, 8 * 3), 256>>>(img, out);
}

// round 4
// speedup vs baseline: 1.3836x; 1.3836x over previous
#include <cuda_runtime.h>
#include <cstddef>

// ---------------------------------------------------------------------------
// Compile-time Gaussian weights (passed BY VALUE so they fold to FFMA-imm)
// ---------------------------------------------------------------------------
constexpr double cexp_pos(double x) {
    double term = 1.0, sum = 1.0;
    for (int i = 1; i < 200; ++i) {
        term *= x / (double)i;
        if (term < 1e-250) break;
        sum += term;
    }
    return sum;
}

template <int KS>
struct Wt { float w[KS]; };

template <int KS>
constexpr Wt<KS> make_w(double sigma) {
    Wt<KS> W{};
    double wd[KS]{};
    double s = 0.0;
    for (int i = 0; i < KS; ++i) {
        double d = (double)(i - KS / 2);
        double e = 1.0 / cexp_pos(d * d / (2.0 * sigma * sigma));
        wd[i] = e;
        s += e;
    }
    for (int i = 0; i < KS; ++i) W.w[i] = (float)(wd[i] / s);
    return W;
}

constexpr Wt<7>   CW0 = make_w<7>(0.6);
constexpr Wt<9>   CW1 = make_w<9>(1.2);
constexpr Wt<17>  CW2 = make_w<17>(2.4);
constexpr Wt<31>  CW3 = make_w<31>(4.8);
constexpr Wt<59>  CW4 = make_w<59>(9.6);
constexpr Wt<117> CW5 = make_w<117>(19.2);

constexpr int H = 512, W = 512;
constexpr int HW = H * W;
constexpr int NROWS = 8 * 3 * H;        // 12288
constexpr int NPIX = NROWS * W;         // 6291456
constexpr int PMAX = 58;

__device__ float g_scratch[6 * (size_t)NPIX];

// ---------------------------------------------------------------------------
// cp.async helpers
// ---------------------------------------------------------------------------
__device__ __forceinline__ void cp_async16(unsigned daddr, const void* gsrc) {
    asm volatile("cp.async.cg.shared.global [%0], [%1], 16;\n"
                 :: "r"(daddr), "l"(gsrc) : "memory");
}
__device__ __forceinline__ void cp_commit() {
    asm volatile("cp.async.commit_group;\n" ::: "memory");
}
template <int N>
__device__ __forceinline__ void cp_wait() {
    asm volatile("cp.async.wait_group %0;\n" :: "n"(N) : "memory");
}

// ---------------------------------------------------------------------------
// Kernel A: horizontal pass. CTA = 256 = 4 rows x 64 threads; 8 px/thread.
// Padded smem row (idx -> idx + idx/8): stride-8 lane access conflict-free.
// ---------------------------------------------------------------------------
template <int KS>
__device__ __forceinline__ void hconv(const Wt<KS> Wc,
                                      const float* __restrict__ sr,
                                      int lane, float* __restrict__ dst) {
    constexpr int P  = KS / 2;
    constexpr int S0 = PMAX - P;
    constexpr int Q  = S0 >> 3;
    constexpr int R  = S0 & 7;
    const int base = 9 * (lane + Q);

    float win[8], acc[8];
#pragma unroll
    for (int i = 0; i < 7; ++i)
        win[i] = sr[base + (R + i) + ((R + i) >> 3)];
#pragma unroll
    for (int t = 0; t < 8; ++t) acc[t] = 0.f;
#pragma unroll
    for (int k = 0; k < KS; ++k) {
        const int j = k + 7;
        win[j & 7] = sr[base + (R + j) + ((R + j) >> 3)];
#pragma unroll
        for (int t = 0; t < 8; ++t)
            acc[t] += Wc.w[k] * win[(k + t) & 7];
    }
    float4* d4 = reinterpret_cast<float4*>(dst + lane * 8);
    d4[0] = make_float4(acc[0], acc[1], acc[2], acc[3]);
    d4[1] = make_float4(acc[4], acc[5], acc[6], acc[7]);
}

__global__ __launch_bounds__(256) void hpass_kernel(const float* __restrict__ img) {
    __shared__ float sr[4][712];
    const int grp = threadIdx.x >> 6;
    const int lt  = threadIdx.x & 63;
    const int row = blockIdx.x * 4 + grp;

    const float* rp = img + (size_t)row * W;
    for (int x = lt; x < W + 2 * PMAX; x += 64) {
        int gx = x - PMAX;
        gx = gx < 0 ? -gx : (gx > W - 1 ? 2 * W - 2 - gx : gx);
        sr[grp][x + (x >> 3)] = rp[gx];
    }
    __syncthreads();

    const float* s = sr[grp];
    float* base = g_scratch + (size_t)row * W;
    hconv<7>(CW0, s, lt, base + 0 * (size_t)NPIX);
    hconv<9>(CW1, s, lt, base + 1 * (size_t)NPIX);
    hconv<17>(CW2, s, lt, base + 2 * (size_t)NPIX);
    hconv<31>(CW3, s, lt, base + 3 * (size_t)NPIX);
    hconv<59>(CW4, s, lt, base + 4 * (size_t)NPIX);
    hconv<117>(CW5, s, lt, base + 5 * (size_t)NPIX);
}

// ---------------------------------------------------------------------------
// Kernel B: vertical pass + DoG. All six sigma tiles prefetched up-front via
// cp.async groups into one dynamic-smem arena; one wait+sync per stage.
// Row offsets (rows of 32 floats): NR = 64+KS-1 -> 70,72,80,94,122,180
// prefix: 0,70,142,222,316,438 ; total 618 rows = 79104 bytes.
// ---------------------------------------------------------------------------
constexpr int VSMEM_BYTES = 618 * 32 * 4;   // 79104

template <int KS, int OFF>
__device__ __forceinline__ void load_tile_async(unsigned smb,
                                                const float* __restrict__ src,
                                                int R0, int tid) {
    constexpr int P  = KS / 2;
    constexpr int NR = 64 + KS - 1;
    const unsigned base = smb + (unsigned)OFF * 128u;
    const int c4 = (tid & 7) * 4;           // float offset of this thread's 16B
#pragma unroll 2
    for (int m = tid >> 3; m < NR; m += 32) {
        int gr = R0 - P + m;
        gr = gr < 0 ? -gr : (gr > H - 1 ? 2 * H - 2 - gr : gr);
        cp_async16(base + (unsigned)(m * 32 + c4) * 4u,
                   src + (size_t)gr * W + c4);
    }
    cp_commit();
}

template <int KS>
__device__ __forceinline__ void vconv(const Wt<KS> Wc,
                                      const float* __restrict__ sm,
                                      int g, int lane, float acc[8]) {
    const int base = g * 8 * 32 + lane;
    float win[8];
#pragma unroll
    for (int i = 0; i < 7; ++i) win[i] = sm[base + i * 32];
#pragma unroll
    for (int t = 0; t < 8; ++t) acc[t] = 0.f;
#pragma unroll
    for (int k = 0; k < KS; ++k) {
        win[(k + 7) & 7] = sm[base + (k + 7) * 32];
#pragma unroll
        for (int t = 0; t < 8; ++t)
            acc[t] += Wc.w[k] * win[(k + t) & 7];
    }
}

__device__ __forceinline__ void store_sub(float* __restrict__ p,
                                          const float acc[8], float prev[8]) {
#pragma unroll
    for (int t = 0; t < 8; ++t) {
        p[(size_t)t * W] = acc[t] - prev[t];
        prev[t] = acc[t];
    }
}

__global__ __launch_bounds__(256) void vpass_kernel(const float* __restrict__ img,
                                                    float* __restrict__ out) {
    extern __shared__ float sm[];
    const int tid  = threadIdx.x;
    const int lane = tid & 31;
    const int g    = tid >> 5;
    const int c0   = blockIdx.x * 32;
    const int R0   = blockIdx.y * 64;
    const int bc   = blockIdx.z;
    const int b    = bc / 3;
    const int ch   = bc - b * 3;
    const int rbase = R0 + g * 8;

    const float* sbase = g_scratch + (size_t)bc * HW + c0;
    const unsigned smb = (unsigned)__cvta_generic_to_shared(sm);

    // prefetch all 6 tiles (6 commit groups, in sigma order)
    load_tile_async<7,     0>(smb, sbase + 0 * (size_t)NPIX, R0, tid);
    load_tile_async<9,    70>(smb, sbase + 1 * (size_t)NPIX, R0, tid);
    load_tile_async<17,  142>(smb, sbase + 2 * (size_t)NPIX, R0, tid);
    load_tile_async<31,  222>(smb, sbase + 3 * (size_t)NPIX, R0, tid);
    load_tile_async<59,  316>(smb, sbase + 4 * (size_t)NPIX, R0, tid);
    load_tile_async<117, 438>(smb, sbase + 5 * (size_t)NPIX, R0, tid);

    // original image values (for subband 0 = G0 - img) — plain LDG, overlaps
    const float* imgp = img + (size_t)bc * HW + c0 + lane;
    float prev[8], acc[8];
#pragma unroll
    for (int t = 0; t < 8; ++t) prev[t] = imgp[(size_t)(rbase + t) * W];

    float* outp = out + ((size_t)b * 21 + ch) * HW + (size_t)rbase * W + c0 + lane;

    cp_wait<5>(); __syncthreads();
    vconv<7>(CW0, sm + 0 * 32, g, lane, acc);
    store_sub(outp + 0 * (size_t)(3 * HW), acc, prev);

    cp_wait<4>(); __syncthreads();
    vconv<9>(CW1, sm + 70 * 32, g, lane, acc);
    store_sub(outp + 1 * (size_t)(3 * HW), acc, prev);

    cp_wait<3>(); __syncthreads();
    vconv<17>(CW2, sm + 142 * 32, g, lane, acc);
    store_sub(outp + 2 * (size_t)(3 * HW), acc, prev);

    cp_wait<2>(); __syncthreads();
    vconv<31>(CW3, sm + 222 * 32, g, lane, acc);
    store_sub(outp + 3 * (size_t)(3 * HW), acc, prev);

    cp_wait<1>(); __syncthreads();
    vconv<59>(CW4, sm + 316 * 32, g, lane, acc);
    store_sub(outp + 4 * (size_t)(3 * HW), acc, prev);

    cp_wait<0>(); __syncthreads();
    vconv<117>(CW5, sm + 438 * 32, g, lane, acc);
    store_sub(outp + 5 * (size_t)(3 * HW), acc, prev);

    // last subband = G5 itself
#pragma unroll
    for (int t = 0; t < 8; ++t)
        outp[6 * (size_t)(3 * HW) + (size_t)t * W] = prev[t];
}

// ---------------------------------------------------------------------------
extern "C" void kernel_launch(void* const* d_in, const int* in_sizes, int n_in,
                              void* d_out, int out_size) {
    const float* img = (const float*)d_in[0];
    float* out = (float*)d_out;

    cudaFuncSetAttribute(vpass_kernel,
                         cudaFuncAttributeMaxDynamicSharedMemorySize,
                         VSMEM_BYTES);

    hpass_kernel<<<NROWS / 4, 256>>>(img);
    vpass_kernel<<<dim3(W / 32, H / 64, 8 * 3), 256, VSMEM_BYTES>>>(img, out);
}